// round 15
// baseline (speedup 1.0000x reference)
#include <cuda_runtime.h>
#include <cuda_bf16.h>
#include <cstdint>

// out[c, n] = sum over (h, k) with octree[h,k]==n of data_in[c, k, h]
// data_in: [C, K, H] f32 ; octree: [H, K] i32 ; out: [C, N] f32, N==H.
//
// Converged configuration (348.9 / 349.5 / 349.7 us across three runs):
//  1) fused prologue: zero [N, C] scratch || transpose octree -> [K, N]
//     (coalesced index reads are worth a full pass: they keep the scatter's
//      L1tex wavefront queue clean — measured +51 us without)
//  2) scatter: per-thread 256B cp.reduce.async.bulk into scratch[idx*64]
//     (full-sector LTS RMW payload; 4.6x over scalar atomics), with the
//     REQUIRED fence.proxy.async between generic-proxy STS and async-proxy
//     TMA reads (omitting it silently corrupts ~1e-2 of the output)
//  3) vectorized [N, 64] -> [64, N] transpose to the output layout.
// Scatter sits at the LTS sector-RMW wall; prologue/epilogue at stream floors.

#define MAX_N 200000
#define CH    64
#define KK    27
#define TILE_H 256
#define SSTR  68   // smem row stride (floats): 272B, float4-STS conflict-free

__device__ float g_scratch[(size_t)MAX_N * CH];      // 51.2 MB, [N, C]
__device__ int   g_octree_t[(size_t)KK * MAX_N];     // 21.6 MB, [K, N]

__device__ __forceinline__ uint32_t smem_u32(const void* p) {
    uint32_t a;
    asm("{ .reg .u64 t; cvta.to.shared.u64 t, %1; cvt.u32.u64 %0, t; }"
        : "=r"(a) : "l"(p));
    return a;
}

// Fused prologue. Blocks [0, tr_blocks): octree [N,K] -> [K,N] transpose
// (int4 both sides for full 128-row tiles). Blocks [tr_blocks, ...): zero the
// [N, C] scratch with float4 stores (4 per thread).
__global__ __launch_bounds__(256) void prologue_kernel(
    const int* __restrict__ oct, int* __restrict__ oct_t,
    float4* __restrict__ scratch4, int n4,
    int K, int N, int tr_blocks)
{
    if ((int)blockIdx.x >= tr_blocks) {
        const int base = ((int)blockIdx.x - tr_blocks) * 256 * 4 + threadIdx.x;
        const float4 z = make_float4(0.f, 0.f, 0.f, 0.f);
        #pragma unroll
        for (int j = 0; j < 4; ++j) {
            const int i = base + j * 256;
            if (i < n4) scratch4[i] = z;
        }
        return;
    }

    __shared__ __align__(16) int tile[128 * KK];     // 13.8 KB
    const int n0  = blockIdx.x * 128;
    const int tid = threadIdx.x;                     // 256
    const int rows = (N - n0 < 128) ? (N - n0) : 128;

    if (rows == 128 && K == KK) {
        const int4* src = reinterpret_cast<const int4*>(oct + (size_t)n0 * KK);
        int4* dst = reinterpret_cast<int4*>(tile);
        for (int i = tid; i < (128 * KK) / 4; i += 256) dst[i] = src[i];
        __syncthreads();
        for (int i = tid; i < KK * 32; i += 256) {
            const int k = i >> 5, m = i & 31;
            int4 v;
            v.x = tile[(4 * m + 0) * KK + k];
            v.y = tile[(4 * m + 1) * KK + k];
            v.z = tile[(4 * m + 2) * KK + k];
            v.w = tile[(4 * m + 3) * KK + k];
            reinterpret_cast<int4*>(oct_t + (size_t)k * N + n0)[m] = v;
        }
    } else {
        const int total = rows * K;
        for (int i = tid; i < total; i += 256) tile[i] = oct[(size_t)n0 * K + i];
        __syncthreads();
        for (int i = tid; i < total; i += 256) {
            const int k = i / rows, j = i - k * rows;
            oct_t[(size_t)k * N + n0 + j] = tile[j * K + k];
        }
    }
}

// Block: 256 h's of one k. Thread t loads all 64 channels of h = h0 + t
// (float4 LDGs, coalesced per channel across the warp) into its smem row.
// fence.proxy.async + __syncthreads makes STS visible to the async proxy,
// then every thread issues one 256B bulk-reduce into scratch[idx*64].
__global__ __launch_bounds__(256) void col2octree_scatter_tma(
    const float* __restrict__ data_in,   // [C, K, N]
    const int*   __restrict__ oct_t,     // [K, N]
    float*       __restrict__ scratch,   // [N, C]
    int K, int N)
{
    __shared__ __align__(16) float tile[TILE_H * SSTR];  // 69.6 KB

    const int k  = blockIdx.y;
    const int h0 = blockIdx.x * TILE_H;
    const int t  = threadIdx.x;          // 256 threads
    const int h  = h0 + t;

    // Prefetch scatter index (coalesced; latency hidden under the load storm).
    int idx = -1;
    if (h < N) idx = __ldg(&oct_t[(size_t)k * N + h]);

    const float* src = data_in + (size_t)k * N + h;
    const size_t cs  = (size_t)K * N;    // channel stride

    if (h < N) {
        #pragma unroll
        for (int q = 0; q < 16; ++q) {
            const int c = q * 4;
            float4 v;
            v.x = __ldcs(src + (size_t)(c + 0) * cs);
            v.y = __ldcs(src + (size_t)(c + 1) * cs);
            v.z = __ldcs(src + (size_t)(c + 2) * cs);
            v.w = __ldcs(src + (size_t)(c + 3) * cs);
            *reinterpret_cast<float4*>(&tile[t * SSTR + c]) = v;
        }
    }
    // Generic-proxy STS -> async-proxy visibility (required for cp.reduce.async.bulk).
    asm volatile("fence.proxy.async.shared::cta;" ::: "memory");
    __syncthreads();

    if (idx >= 0) {
        uint32_t s = smem_u32(&tile[t * SSTR]);
        float* d = scratch + (size_t)idx * CH;
        asm volatile(
            "cp.reduce.async.bulk.global.shared::cta.bulk_group.add.f32 "
            "[%0], [%1], %2;"
            :: "l"(d), "r"(s), "r"((uint32_t)(CH * 4))
            : "memory");
    }
    asm volatile("cp.async.bulk.commit_group;" ::: "memory");
    asm volatile("cp.async.bulk.wait_group 0;" ::: "memory");
}

// Fallback scalar-v4 scatter (only if C != 64)
__global__ void col2octree_scatter_v4(
    const float* __restrict__ data_in, const int* __restrict__ oct_t,
    float* __restrict__ scratch, int C, int K, int N)
{
    const int h = blockIdx.x * blockDim.x + threadIdx.x;
    const int k = blockIdx.y;
    if (h >= N) return;
    const int idx = __ldg(&oct_t[(size_t)k * N + h]);
    if (idx < 0) return;
    const float* src = data_in + (size_t)k * N + h;
    const size_t cs = (size_t)K * N;
    float* dst = scratch + (size_t)idx * C;
    for (int c = 0; c + 4 <= C; c += 4) {
        float a = __ldcs(src + (size_t)(c + 0) * cs);
        float b = __ldcs(src + (size_t)(c + 1) * cs);
        float d = __ldcs(src + (size_t)(c + 2) * cs);
        float e = __ldcs(src + (size_t)(c + 3) * cs);
        asm volatile("red.global.add.v4.f32 [%0], {%1, %2, %3, %4};"
                     :: "l"(dst + c), "f"(a), "f"(b), "f"(d), "f"(e) : "memory");
    }
}

// [N, 64] -> [64, N] transpose, float4 both sides. Requires N % 32 == 0.
__global__ __launch_bounds__(256) void transpose_nc_to_cn_v4(
    const float* __restrict__ scratch, float* __restrict__ out, int N)
{
    __shared__ float tile[64][33];
    const int n0   = blockIdx.x * 32;
    const int t    = threadIdx.x;
    const int lane = t & 31;
    const int q    = t >> 5;                 // 0..7

    const float4* src = reinterpret_cast<const float4*>(scratch + (size_t)(n0 + lane) * 64);
    float4 a = __ldcs(&src[2 * q]);
    float4 b = __ldcs(&src[2 * q + 1]);
    tile[8 * q + 0][lane] = a.x;
    tile[8 * q + 1][lane] = a.y;
    tile[8 * q + 2][lane] = a.z;
    tile[8 * q + 3][lane] = a.w;
    tile[8 * q + 4][lane] = b.x;
    tile[8 * q + 5][lane] = b.y;
    tile[8 * q + 6][lane] = b.z;
    tile[8 * q + 7][lane] = b.w;
    __syncthreads();

    #pragma unroll
    for (int iter = 0; iter < 2; ++iter) {
        const int i = t + 256 * iter;        // 0..511
        const int c = i >> 3;
        const int m = i & 7;
        float4 v;
        v.x = tile[c][4 * m + 0];
        v.y = tile[c][4 * m + 1];
        v.z = tile[c][4 * m + 2];
        v.w = tile[c][4 * m + 3];
        *reinterpret_cast<float4*>(out + (size_t)c * N + n0 + 4 * m) = v;
    }
}

// Generic fallback transpose.
__global__ void transpose_nc_to_cn(
    const float* __restrict__ scratch, float* __restrict__ out, int C, int N)
{
    __shared__ float tile[32][33];
    const int n0 = blockIdx.x * 32;
    const int c0 = blockIdx.y * 32;
    const int tx = threadIdx.x;
    const int ty = threadIdx.y;
    #pragma unroll
    for (int i = ty; i < 32; i += 8) {
        int n = n0 + i, c = c0 + tx;
        tile[i][tx] = (n < N && c < C) ? scratch[(size_t)n * C + c] : 0.f;
    }
    __syncthreads();
    #pragma unroll
    for (int i = ty; i < 32; i += 8) {
        int c = c0 + i, n = n0 + tx;
        if (n < N && c < C) out[(size_t)c * N + n] = tile[tx][i];
    }
}

extern "C" void kernel_launch(void* const* d_in, const int* in_sizes, int n_in,
                              void* d_out, int out_size) {
    const float* data_in = (const float*)d_in[0];
    const int*   octree  = (const int*)d_in[1];
    float*       out     = (float*)d_out;

    const long long in0 = in_sizes[0];          // C*K*N
    const long long in1 = in_sizes[1];          // N*K
    const int C = (int)(in0 / in1);             // 64
    const int K = (int)(in0 / out_size);        // 27
    const int N = (int)(out_size / C);          // 200000

    float* scratch_ptr = nullptr;
    int*   oct_t_ptr   = nullptr;
    cudaGetSymbolAddress((void**)&scratch_ptr, g_scratch);
    cudaGetSymbolAddress((void**)&oct_t_ptr, g_octree_t);

    // 1) fused prologue: transpose octree || zero scratch
    {
        const int tr_blocks = (N + 127) / 128;
        const int n4 = (N * C) / 4;                       // float4 count
        const int z_blocks = (n4 + 256 * 4 - 1) / (256 * 4);
        prologue_kernel<<<tr_blocks + z_blocks, 256>>>(
            octree, oct_t_ptr, (float4*)scratch_ptr, n4, K, N, tr_blocks);
    }

    // 2) scatter-add
    if (C == CH) {
        dim3 blocks((N + TILE_H - 1) / TILE_H, K, 1);
        col2octree_scatter_tma<<<blocks, 256>>>(data_in, oct_t_ptr, scratch_ptr, K, N);
    } else {
        dim3 blocks((N + 255) / 256, K, 1);
        col2octree_scatter_v4<<<blocks, 256>>>(data_in, oct_t_ptr, scratch_ptr, C, K, N);
    }

    // 3) transpose [N, C] -> [C, N]
    if (C == CH && (N & 31) == 0) {
        transpose_nc_to_cn_v4<<<N / 32, 256>>>(scratch_ptr, out, N);
    } else {
        dim3 threads(32, 8, 1);
        dim3 blocks((N + 31) / 32, (C + 31) / 32, 1);
        transpose_nc_to_cn<<<blocks, threads>>>(scratch_ptr, out, C, N);
    }
}

// round 16
// speedup vs baseline: 1.0072x; 1.0072x over previous
#include <cuda_runtime.h>
#include <cuda_bf16.h>
#include <cstdint>

// out[c, n] = sum over (h, k) with octree[h,k]==n of data_in[c, k, h]
// data_in: [C, K, H] f32 ; octree: [H, K] i32 ; out: [C, N] f32, N==H.
//
// Converged configuration (348.9 / 349.5 / 349.7 / 350.9 us across four runs):
//  1) fused prologue: zero [N, C] scratch || transpose octree -> [K, N]
//     (coalesced index reads keep the scatter's L1tex wavefront queue clean;
//      measured +51 us without this pass)
//  2) scatter: per-thread 256B cp.reduce.async.bulk into scratch[idx*64]
//     (full-sector LTS RMW payload; 4.6x over scalar atomics), with the
//     REQUIRED fence.proxy.async between generic-proxy STS and async-proxy
//     TMA reads (omitting it silently corrupts ~1e-2 of the output)
//  3) vectorized [N, 64] -> [64, N] transpose to the output layout.
// Scatter sits at the LTS sector-RMW wall; prologue/epilogue at stream floors.

#define MAX_N 200000
#define CH    64
#define KK    27
#define TILE_H 256
#define SSTR  68   // smem row stride (floats): 272B, float4-STS conflict-free

__device__ float g_scratch[(size_t)MAX_N * CH];      // 51.2 MB, [N, C]
__device__ int   g_octree_t[(size_t)KK * MAX_N];     // 21.6 MB, [K, N]

__device__ __forceinline__ uint32_t smem_u32(const void* p) {
    uint32_t a;
    asm("{ .reg .u64 t; cvta.to.shared.u64 t, %1; cvt.u32.u64 %0, t; }"
        : "=r"(a) : "l"(p));
    return a;
}

// Fused prologue. Blocks [0, tr_blocks): octree [N,K] -> [K,N] transpose
// (int4 both sides for full 128-row tiles). Blocks [tr_blocks, ...): zero the
// [N, C] scratch with float4 stores (4 per thread).
__global__ __launch_bounds__(256) void prologue_kernel(
    const int* __restrict__ oct, int* __restrict__ oct_t,
    float4* __restrict__ scratch4, int n4,
    int K, int N, int tr_blocks)
{
    if ((int)blockIdx.x >= tr_blocks) {
        const int base = ((int)blockIdx.x - tr_blocks) * 256 * 4 + threadIdx.x;
        const float4 z = make_float4(0.f, 0.f, 0.f, 0.f);
        #pragma unroll
        for (int j = 0; j < 4; ++j) {
            const int i = base + j * 256;
            if (i < n4) scratch4[i] = z;
        }
        return;
    }

    __shared__ __align__(16) int tile[128 * KK];     // 13.8 KB
    const int n0  = blockIdx.x * 128;
    const int tid = threadIdx.x;                     // 256
    const int rows = (N - n0 < 128) ? (N - n0) : 128;

    if (rows == 128 && K == KK) {
        const int4* src = reinterpret_cast<const int4*>(oct + (size_t)n0 * KK);
        int4* dst = reinterpret_cast<int4*>(tile);
        for (int i = tid; i < (128 * KK) / 4; i += 256) dst[i] = src[i];
        __syncthreads();
        for (int i = tid; i < KK * 32; i += 256) {
            const int k = i >> 5, m = i & 31;
            int4 v;
            v.x = tile[(4 * m + 0) * KK + k];
            v.y = tile[(4 * m + 1) * KK + k];
            v.z = tile[(4 * m + 2) * KK + k];
            v.w = tile[(4 * m + 3) * KK + k];
            reinterpret_cast<int4*>(oct_t + (size_t)k * N + n0)[m] = v;
        }
    } else {
        const int total = rows * K;
        for (int i = tid; i < total; i += 256) tile[i] = oct[(size_t)n0 * K + i];
        __syncthreads();
        for (int i = tid; i < total; i += 256) {
            const int k = i / rows, j = i - k * rows;
            oct_t[(size_t)k * N + n0 + j] = tile[j * K + k];
        }
    }
}

// Block: 256 h's of one k. Thread t loads all 64 channels of h = h0 + t
// (float4 LDGs, coalesced per channel across the warp) into its smem row.
// fence.proxy.async + __syncthreads makes STS visible to the async proxy,
// then every thread issues one 256B bulk-reduce into scratch[idx*64].
__global__ __launch_bounds__(256) void col2octree_scatter_tma(
    const float* __restrict__ data_in,   // [C, K, N]
    const int*   __restrict__ oct_t,     // [K, N]
    float*       __restrict__ scratch,   // [N, C]
    int K, int N)
{
    __shared__ __align__(16) float tile[TILE_H * SSTR];  // 69.6 KB

    const int k  = blockIdx.y;
    const int h0 = blockIdx.x * TILE_H;
    const int t  = threadIdx.x;          // 256 threads
    const int h  = h0 + t;

    // Prefetch scatter index (coalesced; latency hidden under the load storm).
    int idx = -1;
    if (h < N) idx = __ldg(&oct_t[(size_t)k * N + h]);

    const float* src = data_in + (size_t)k * N + h;
    const size_t cs  = (size_t)K * N;    // channel stride

    if (h < N) {
        #pragma unroll
        for (int q = 0; q < 16; ++q) {
            const int c = q * 4;
            float4 v;
            v.x = __ldcs(src + (size_t)(c + 0) * cs);
            v.y = __ldcs(src + (size_t)(c + 1) * cs);
            v.z = __ldcs(src + (size_t)(c + 2) * cs);
            v.w = __ldcs(src + (size_t)(c + 3) * cs);
            *reinterpret_cast<float4*>(&tile[t * SSTR + c]) = v;
        }
    }
    // Generic-proxy STS -> async-proxy visibility (required for cp.reduce.async.bulk).
    asm volatile("fence.proxy.async.shared::cta;" ::: "memory");
    __syncthreads();

    if (idx >= 0) {
        uint32_t s = smem_u32(&tile[t * SSTR]);
        float* d = scratch + (size_t)idx * CH;
        asm volatile(
            "cp.reduce.async.bulk.global.shared::cta.bulk_group.add.f32 "
            "[%0], [%1], %2;"
            :: "l"(d), "r"(s), "r"((uint32_t)(CH * 4))
            : "memory");
    }
    asm volatile("cp.async.bulk.commit_group;" ::: "memory");
    asm volatile("cp.async.bulk.wait_group 0;" ::: "memory");
}

// Fallback scalar-v4 scatter (only if C != 64)
__global__ void col2octree_scatter_v4(
    const float* __restrict__ data_in, const int* __restrict__ oct_t,
    float* __restrict__ scratch, int C, int K, int N)
{
    const int h = blockIdx.x * blockDim.x + threadIdx.x;
    const int k = blockIdx.y;
    if (h >= N) return;
    const int idx = __ldg(&oct_t[(size_t)k * N + h]);
    if (idx < 0) return;
    const float* src = data_in + (size_t)k * N + h;
    const size_t cs = (size_t)K * N;
    float* dst = scratch + (size_t)idx * C;
    for (int c = 0; c + 4 <= C; c += 4) {
        float a = __ldcs(src + (size_t)(c + 0) * cs);
        float b = __ldcs(src + (size_t)(c + 1) * cs);
        float d = __ldcs(src + (size_t)(c + 2) * cs);
        float e = __ldcs(src + (size_t)(c + 3) * cs);
        asm volatile("red.global.add.v4.f32 [%0], {%1, %2, %3, %4};"
                     :: "l"(dst + c), "f"(a), "f"(b), "f"(d), "f"(e) : "memory");
    }
}

// [N, 64] -> [64, N] transpose, float4 both sides. Requires N % 32 == 0.
__global__ __launch_bounds__(256) void transpose_nc_to_cn_v4(
    const float* __restrict__ scratch, float* __restrict__ out, int N)
{
    __shared__ float tile[64][33];
    const int n0   = blockIdx.x * 32;
    const int t    = threadIdx.x;
    const int lane = t & 31;
    const int q    = t >> 5;                 // 0..7

    const float4* src = reinterpret_cast<const float4*>(scratch + (size_t)(n0 + lane) * 64);
    float4 a = __ldcs(&src[2 * q]);
    float4 b = __ldcs(&src[2 * q + 1]);
    tile[8 * q + 0][lane] = a.x;
    tile[8 * q + 1][lane] = a.y;
    tile[8 * q + 2][lane] = a.z;
    tile[8 * q + 3][lane] = a.w;
    tile[8 * q + 4][lane] = b.x;
    tile[8 * q + 5][lane] = b.y;
    tile[8 * q + 6][lane] = b.z;
    tile[8 * q + 7][lane] = b.w;
    __syncthreads();

    #pragma unroll
    for (int iter = 0; iter < 2; ++iter) {
        const int i = t + 256 * iter;        // 0..511
        const int c = i >> 3;
        const int m = i & 7;
        float4 v;
        v.x = tile[c][4 * m + 0];
        v.y = tile[c][4 * m + 1];
        v.z = tile[c][4 * m + 2];
        v.w = tile[c][4 * m + 3];
        *reinterpret_cast<float4*>(out + (size_t)c * N + n0 + 4 * m) = v;
    }
}

// Generic fallback transpose.
__global__ void transpose_nc_to_cn(
    const float* __restrict__ scratch, float* __restrict__ out, int C, int N)
{
    __shared__ float tile[32][33];
    const int n0 = blockIdx.x * 32;
    const int c0 = blockIdx.y * 32;
    const int tx = threadIdx.x;
    const int ty = threadIdx.y;
    #pragma unroll
    for (int i = ty; i < 32; i += 8) {
        int n = n0 + i, c = c0 + tx;
        tile[i][tx] = (n < N && c < C) ? scratch[(size_t)n * C + c] : 0.f;
    }
    __syncthreads();
    #pragma unroll
    for (int i = ty; i < 32; i += 8) {
        int c = c0 + i, n = n0 + tx;
        if (n < N && c < C) out[(size_t)c * N + n] = tile[tx][i];
    }
}

extern "C" void kernel_launch(void* const* d_in, const int* in_sizes, int n_in,
                              void* d_out, int out_size) {
    const float* data_in = (const float*)d_in[0];
    const int*   octree  = (const int*)d_in[1];
    float*       out     = (float*)d_out;

    const long long in0 = in_sizes[0];          // C*K*N
    const long long in1 = in_sizes[1];          // N*K
    const int C = (int)(in0 / in1);             // 64
    const int K = (int)(in0 / out_size);        // 27
    const int N = (int)(out_size / C);          // 200000

    float* scratch_ptr = nullptr;
    int*   oct_t_ptr   = nullptr;
    cudaGetSymbolAddress((void**)&scratch_ptr, g_scratch);
    cudaGetSymbolAddress((void**)&oct_t_ptr, g_octree_t);

    // 1) fused prologue: transpose octree || zero scratch
    {
        const int tr_blocks = (N + 127) / 128;
        const int n4 = (N * C) / 4;                       // float4 count
        const int z_blocks = (n4 + 256 * 4 - 1) / (256 * 4);
        prologue_kernel<<<tr_blocks + z_blocks, 256>>>(
            octree, oct_t_ptr, (float4*)scratch_ptr, n4, K, N, tr_blocks);
    }

    // 2) scatter-add
    if (C == CH) {
        dim3 blocks((N + TILE_H - 1) / TILE_H, K, 1);
        col2octree_scatter_tma<<<blocks, 256>>>(data_in, oct_t_ptr, scratch_ptr, K, N);
    } else {
        dim3 blocks((N + 255) / 256, K, 1);
        col2octree_scatter_v4<<<blocks, 256>>>(data_in, oct_t_ptr, scratch_ptr, C, K, N);
    }

    // 3) transpose [N, C] -> [C, N]
    if (C == CH && (N & 31) == 0) {
        transpose_nc_to_cn_v4<<<N / 32, 256>>>(scratch_ptr, out, N);
    } else {
        dim3 threads(32, 8, 1);
        dim3 blocks((N + 31) / 32, (C + 31) / 32, 1);
        transpose_nc_to_cn<<<blocks, threads>>>(scratch_ptr, out, C, N);
    }
}